// round 5
// baseline (speedup 1.0000x reference)
#include <cuda_runtime.h>
#include <cuda_bf16.h>
#include <cstdint>

// LRML: out[b] = -|| ue + rel - ie ||^2
// Layout: 16 lanes per row, each lane owns 2 of D=32 dims via one float2
// per table. 2 rows/warp, 8192 warps total -> 2x outstanding-gather product
// vs previous rounds (latency-bound regime). Reductions = 4 shfl_xor.

#define D 32
#define M 10
#define ROWS_PER_WARP 2
#define WARPS_PER_BLOCK 8
#define THREADS (WARPS_PER_BLOCK * 32)
#define ROWS_PER_BLOCK (WARPS_PER_BLOCK * ROWS_PER_WARP)

__device__ __forceinline__ float half_sum(float v) {
    v += __shfl_xor_sync(0xFFFFFFFFu, v, 1);
    v += __shfl_xor_sync(0xFFFFFFFFu, v, 2);
    v += __shfl_xor_sync(0xFFFFFFFFu, v, 4);
    v += __shfl_xor_sync(0xFFFFFFFFu, v, 8);
    return v;
}

__global__ __launch_bounds__(THREADS)
void lrml_kernel(const int* __restrict__ user_ids,
                 const int* __restrict__ item_ids,
                 const float* __restrict__ user_emb,
                 const float* __restrict__ item_emb,
                 const float* __restrict__ W_att,
                 const float* __restrict__ memory,
                 float* __restrict__ out,
                 int B)
{
    __shared__ float2 sW[M * 16];    // W_att rows as float2 (10 x 32 floats)
    __shared__ float2 sMem[M * 16];  // memory rows as float2

    const int lane = threadIdx.x & 31;
    const int h    = lane & 15;       // which 2-dim slice (0..15)
    const int r    = lane >> 4;       // row within warp (0..1)
    const int warp = threadIdx.x >> 5;
    int row = blockIdx.x * ROWS_PER_BLOCK + warp * ROWS_PER_WARP + r;
    const bool valid = (row < B);
    if (row >= B) row = B - 1;        // clamp so all threads can sync/participate

    // Issue id loads first: their latency overlaps the weight staging below.
    const int uid = __ldg(&user_ids[row]);
    const int iid = __ldg(&item_ids[row]);

    // Stage the tiny weight matrices (160 float2 each) — independent of ids.
    for (int idx = threadIdx.x; idx < M * 16; idx += THREADS) {
        sW[idx]   = ((const float2*)W_att)[idx];
        sMem[idx] = ((const float2*)memory)[idx];
    }

    // Gathers: one 128B line per (row, table), 2 in flight per thread.
    float2 u = __ldg((const float2*)(user_emb + (size_t)uid * D + h * 2));
    float2 i = __ldg((const float2*)(item_emb + (size_t)iid * D + h * 2));

    __syncthreads();

    float ue0 = u.x, ue1 = u.y;
    float ie0 = i.x, ie1 = i.y;

    // max_norm=1 renorm
    float us = half_sum(fmaf(ue0, ue0, ue1 * ue1));
    float is = half_sum(fmaf(ie0, ie0, ie1 * ie1));
    const float un = sqrtf(us), in = sqrtf(is);
    const float uscale = (un > 1.0f) ? (1.0f / un) : 1.0f;
    const float iscale = (in > 1.0f) ? (1.0f / in) : 1.0f;
    ue0 *= uscale; ue1 *= uscale;
    ie0 *= iscale; ie1 *= iscale;

    const float j0 = ue0 * ie0;
    const float j1 = ue1 * ie1;

    // scores[m] = joint . W_att[m], reduced over 16 lanes
    float sc[M];
    #pragma unroll
    for (int m = 0; m < M; m++) {
        const float2 w = sW[m * 16 + h];
        sc[m] = half_sum(fmaf(j0, w.x, j1 * w.y));
    }

    // softmax over M=10 (all 16 lanes hold identical sc[]); normalization
    // folded into a single post-scale of rel.
    float mx = sc[0];
    #pragma unroll
    for (int m = 1; m < M; m++) mx = fmaxf(mx, sc[m]);
    float denom = 0.0f;
    #pragma unroll
    for (int m = 0; m < M; m++) { sc[m] = __expf(sc[m] - mx); denom += sc[m]; }
    const float inv_denom = 1.0f / denom;

    // rel[j] = (sum_m sc[m] * memory[m][h*2+j]) * inv_denom
    float rel0 = 0.0f, rel1 = 0.0f;
    #pragma unroll
    for (int m = 0; m < M; m++) {
        const float2 mm = sMem[m * 16 + h];
        rel0 = fmaf(sc[m], mm.x, rel0);
        rel1 = fmaf(sc[m], mm.y, rel1);
    }
    rel0 *= inv_denom;
    rel1 *= inv_denom;

    const float d0 = ue0 + rel0 - ie0;
    const float d1 = ue1 + rel1 - ie1;
    const float dist = half_sum(fmaf(d0, d0, d1 * d1));

    if (h == 0 && valid) out[row] = -dist;
}

extern "C" void kernel_launch(void* const* d_in, const int* in_sizes, int n_in,
                              void* d_out, int out_size)
{
    const int*   user_ids = (const int*)  d_in[0];
    const int*   item_ids = (const int*)  d_in[1];
    const float* user_emb = (const float*)d_in[2];
    const float* item_emb = (const float*)d_in[3];
    const float* W_att    = (const float*)d_in[4];
    const float* memory   = (const float*)d_in[5];
    float*       out      = (float*)d_out;

    const int B = in_sizes[0];
    const int grid = (B + ROWS_PER_BLOCK - 1) / ROWS_PER_BLOCK;
    lrml_kernel<<<grid, THREADS>>>(user_ids, item_ids, user_emb, item_emb,
                                   W_att, memory, out, B);
}

// round 6
// speedup vs baseline: 1.0036x; 1.0036x over previous
#include <cuda_runtime.h>
#include <cuda_bf16.h>
#include <cstdint>

// LRML: out[b] = -|| ue + rel - ie ||^2
// 8 lanes/row (lane owns 4 dims, one float4 per table), 4 rows per
// iteration, NITER=2 iterations per warp => 8 rows/warp, 2048 warps.
// ALL id loads and ALL 8 gather LDG.128s are issued before any compute:
// the two DRAM round trips (ids, gathers) are paid once per warp and
// overlap across iterations, instead of serializing per row batch.

#define D 32
#define M 10
#define WARPS_PER_BLOCK 8
#define THREADS (WARPS_PER_BLOCK * 32)
#define ROWS_PER_ITER 4
#define NITER 2
#define ROWS_PER_WARP (ROWS_PER_ITER * NITER)          // 8
#define ROWS_PER_BLOCK (WARPS_PER_BLOCK * ROWS_PER_WARP) // 64

__device__ __forceinline__ float oct_sum(float v) {
    v += __shfl_xor_sync(0xFFFFFFFFu, v, 1);
    v += __shfl_xor_sync(0xFFFFFFFFu, v, 2);
    v += __shfl_xor_sync(0xFFFFFFFFu, v, 4);
    return v;
}

__device__ __forceinline__ void compute_row(
    float4 u, float4 i, int s8,
    const float4* __restrict__ sW, const float4* __restrict__ sMem,
    float* __restrict__ out, int row, bool valid)
{
    float ue[4] = {u.x, u.y, u.z, u.w};
    float ie[4] = {i.x, i.y, i.z, i.w};

    float us = 0.f, is = 0.f;
    #pragma unroll
    for (int j = 0; j < 4; j++) { us = fmaf(ue[j], ue[j], us); is = fmaf(ie[j], ie[j], is); }
    us = oct_sum(us);
    is = oct_sum(is);
    const float un = sqrtf(us), in = sqrtf(is);
    const float uscale = (un > 1.0f) ? (1.0f / un) : 1.0f;
    const float iscale = (in > 1.0f) ? (1.0f / in) : 1.0f;
    #pragma unroll
    for (int j = 0; j < 4; j++) { ue[j] *= uscale; ie[j] *= iscale; }

    float joint[4];
    #pragma unroll
    for (int j = 0; j < 4; j++) joint[j] = ue[j] * ie[j];

    float sc[M];
    #pragma unroll
    for (int m = 0; m < M; m++) {
        const float4 w = sW[m * 8 + s8];
        float p = joint[0] * w.x;
        p = fmaf(joint[1], w.y, p);
        p = fmaf(joint[2], w.z, p);
        p = fmaf(joint[3], w.w, p);
        sc[m] = oct_sum(p);
    }

    float mx = sc[0];
    #pragma unroll
    for (int m = 1; m < M; m++) mx = fmaxf(mx, sc[m]);
    float denom = 0.0f;
    #pragma unroll
    for (int m = 0; m < M; m++) { sc[m] = __expf(sc[m] - mx); denom += sc[m]; }
    const float inv_denom = 1.0f / denom;

    float rel[4] = {0, 0, 0, 0};
    #pragma unroll
    for (int m = 0; m < M; m++) {
        const float4 mm = sMem[m * 8 + s8];
        rel[0] = fmaf(sc[m], mm.x, rel[0]);
        rel[1] = fmaf(sc[m], mm.y, rel[1]);
        rel[2] = fmaf(sc[m], mm.z, rel[2]);
        rel[3] = fmaf(sc[m], mm.w, rel[3]);
    }

    float dist = 0.0f;
    #pragma unroll
    for (int j = 0; j < 4; j++) {
        const float diff = fmaf(rel[j], inv_denom, ue[j] - ie[j]);
        dist = fmaf(diff, diff, dist);
    }
    dist = oct_sum(dist);

    if (s8 == 0 && valid) out[row] = -dist;
}

__global__ __launch_bounds__(THREADS)
void lrml_kernel(const int* __restrict__ user_ids,
                 const int* __restrict__ item_ids,
                 const float* __restrict__ user_emb,
                 const float* __restrict__ item_emb,
                 const float* __restrict__ W_att,
                 const float* __restrict__ memory,
                 float* __restrict__ out,
                 int B)
{
    __shared__ float4 sW[M * 8];
    __shared__ float4 sMem[M * 8];

    const int lane = threadIdx.x & 31;
    const int s8   = lane & 7;       // dim slice (0..7)
    const int r    = lane >> 3;      // row within iteration (0..3)
    const int warp = threadIdx.x >> 5;

    int row0 = blockIdx.x * ROWS_PER_BLOCK + warp * ROWS_PER_WARP + r;
    int row1 = row0 + ROWS_PER_ITER;
    const bool v0 = (row0 < B);
    const bool v1 = (row1 < B);
    if (row0 >= B) row0 = B - 1;
    if (row1 >= B) row1 = B - 1;

    // ---- Phase 1: issue ALL loads up front ----
    const int uid0 = __ldg(&user_ids[row0]);
    const int iid0 = __ldg(&item_ids[row0]);
    const int uid1 = __ldg(&user_ids[row1]);
    const int iid1 = __ldg(&item_ids[row1]);

    const float4 u0 = __ldg((const float4*)(user_emb + (size_t)uid0 * D + s8 * 4));
    const float4 i0 = __ldg((const float4*)(item_emb + (size_t)iid0 * D + s8 * 4));
    const float4 u1 = __ldg((const float4*)(user_emb + (size_t)uid1 * D + s8 * 4));
    const float4 i1 = __ldg((const float4*)(item_emb + (size_t)iid1 * D + s8 * 4));

    // Weight staging (independent of ids/gathers; overlaps their latency)
    for (int idx = threadIdx.x; idx < M * 8; idx += THREADS) {
        sW[idx]   = ((const float4*)W_att)[idx];
        sMem[idx] = ((const float4*)memory)[idx];
    }
    __syncthreads();

    // ---- Phase 2: compute both iterations (gathers already in flight) ----
    compute_row(u0, i0, s8, sW, sMem, out, row0, v0);
    compute_row(u1, i1, s8, sW, sMem, out, row1, v1);
}

extern "C" void kernel_launch(void* const* d_in, const int* in_sizes, int n_in,
                              void* d_out, int out_size)
{
    const int*   user_ids = (const int*)  d_in[0];
    const int*   item_ids = (const int*)  d_in[1];
    const float* user_emb = (const float*)d_in[2];
    const float* item_emb = (const float*)d_in[3];
    const float* W_att    = (const float*)d_in[4];
    const float* memory   = (const float*)d_in[5];
    float*       out      = (float*)d_out;

    const int B = in_sizes[0];
    const int grid = (B + ROWS_PER_BLOCK - 1) / ROWS_PER_BLOCK;
    lrml_kernel<<<grid, THREADS>>>(user_ids, item_ids, user_emb, item_emb,
                                   W_att, memory, out, B);
}

// round 7
// speedup vs baseline: 1.2977x; 1.2930x over previous
#include <cuda_runtime.h>
#include <cuda_bf16.h>
#include <cstdint>

// LRML: out[b] = -|| ue + rel - ie ||^2
// Extreme mapping: 2 lanes per row, each lane owns 16 of D=32 dims
// (two float4 per table). 16 rows/warp, 1024 warps, 128 blocks
// (< 1 block/SM, single wave). All reductions are ONE shfl_xor.
// ~30 warp-instructions per row, gather latency paid once per 16 rows.

#define D 32
#define M 10
#define WARPS_PER_BLOCK 8
#define THREADS (WARPS_PER_BLOCK * 32)
#define ROWS_PER_WARP 16
#define ROWS_PER_BLOCK (WARPS_PER_BLOCK * ROWS_PER_WARP)  // 128

__global__ __launch_bounds__(THREADS)
void lrml_kernel(const int* __restrict__ user_ids,
                 const int* __restrict__ item_ids,
                 const float* __restrict__ user_emb,
                 const float* __restrict__ item_emb,
                 const float* __restrict__ W_att,
                 const float* __restrict__ memory,
                 float* __restrict__ out,
                 int B)
{
    __shared__ float4 sW[M * 8];    // 10 rows x 32 floats as float4
    __shared__ float4 sMem[M * 8];

    const int lane = threadIdx.x & 31;
    const int p    = lane & 1;        // which 16-dim half
    const int r    = lane >> 1;       // row within warp (0..15)
    const int warp = threadIdx.x >> 5;

    int row = blockIdx.x * ROWS_PER_BLOCK + warp * ROWS_PER_WARP + r;
    const bool valid = (row < B);
    if (row >= B) row = B - 1;

    // ids first (latency overlaps weight staging)
    const int uid = __ldg(&user_ids[row]);
    const int iid = __ldg(&item_ids[row]);

    for (int idx = threadIdx.x; idx < M * 8; idx += THREADS) {
        sW[idx]   = ((const float4*)W_att)[idx];
        sMem[idx] = ((const float4*)memory)[idx];
    }

    // Gathers: each lane reads 64B of its row from each table (2x LDG.128).
    const float4* up = (const float4*)(user_emb + (size_t)uid * D + p * 16);
    const float4* ip = (const float4*)(item_emb + (size_t)iid * D + p * 16);
    const float4 u0 = __ldg(up);
    const float4 u1 = __ldg(up + 1);
    const float4 u2 = __ldg(up + 2);
    const float4 u3 = __ldg(up + 3);
    const float4 i0 = __ldg(ip);
    const float4 i1 = __ldg(ip + 1);
    const float4 i2 = __ldg(ip + 2);
    const float4 i3 = __ldg(ip + 3);

    __syncthreads();

    float ue[16] = {u0.x,u0.y,u0.z,u0.w, u1.x,u1.y,u1.z,u1.w,
                    u2.x,u2.y,u2.z,u2.w, u3.x,u3.y,u3.z,u3.w};
    float ie[16] = {i0.x,i0.y,i0.z,i0.w, i1.x,i1.y,i1.z,i1.w,
                    i2.x,i2.y,i2.z,i2.w, i3.x,i3.y,i3.z,i3.w};

    // max_norm=1 renorm (reduction = 1 shfl)
    float us = 0.f, is = 0.f;
    #pragma unroll
    for (int j = 0; j < 16; j++) { us = fmaf(ue[j], ue[j], us); is = fmaf(ie[j], ie[j], is); }
    us += __shfl_xor_sync(0xFFFFFFFFu, us, 1);
    is += __shfl_xor_sync(0xFFFFFFFFu, is, 1);
    const float un = sqrtf(us), in = sqrtf(is);
    const float uscale = (un > 1.0f) ? (1.0f / un) : 1.0f;
    const float iscale = (in > 1.0f) ? (1.0f / in) : 1.0f;
    #pragma unroll
    for (int j = 0; j < 16; j++) { ue[j] *= uscale; ie[j] *= iscale; }

    float joint[16];
    #pragma unroll
    for (int j = 0; j < 16; j++) joint[j] = ue[j] * ie[j];

    // scores[m] = joint . W_att[m] (partial over 16 dims + 1 shfl)
    float sc[M];
    #pragma unroll
    for (int m = 0; m < M; m++) {
        const float4* w = &sW[m * 8 + p * 4];
        const float4 w0 = w[0], w1 = w[1], w2 = w[2], w3 = w[3];
        float a = joint[0] * w0.x;
        float b = joint[1] * w0.y;
        a = fmaf(joint[2],  w0.z, a);
        b = fmaf(joint[3],  w0.w, b);
        a = fmaf(joint[4],  w1.x, a);
        b = fmaf(joint[5],  w1.y, b);
        a = fmaf(joint[6],  w1.z, a);
        b = fmaf(joint[7],  w1.w, b);
        a = fmaf(joint[8],  w2.x, a);
        b = fmaf(joint[9],  w2.y, b);
        a = fmaf(joint[10], w2.z, a);
        b = fmaf(joint[11], w2.w, b);
        a = fmaf(joint[12], w3.x, a);
        b = fmaf(joint[13], w3.y, b);
        a = fmaf(joint[14], w3.z, a);
        b = fmaf(joint[15], w3.w, b);
        float s = a + b;
        s += __shfl_xor_sync(0xFFFFFFFFu, s, 1);
        sc[m] = s;
    }

    // softmax over M=10, done redundantly in both lanes of the pair
    float mx = sc[0];
    #pragma unroll
    for (int m = 1; m < M; m++) mx = fmaxf(mx, sc[m]);
    float denom = 0.0f;
    #pragma unroll
    for (int m = 0; m < M; m++) { sc[m] = __expf(sc[m] - mx); denom += sc[m]; }
    const float inv_denom = 1.0f / denom;

    // rel[j] = sum_m sc[m] * memory[m][p*16+j]  (normalization folded in later)
    float rel[16];
    #pragma unroll
    for (int j = 0; j < 16; j++) rel[j] = 0.0f;
    #pragma unroll
    for (int m = 0; m < M; m++) {
        const float4* mmp = &sMem[m * 8 + p * 4];
        const float4 m0 = mmp[0], m1 = mmp[1], m2 = mmp[2], m3 = mmp[3];
        const float s = sc[m];
        rel[0]  = fmaf(s, m0.x, rel[0]);
        rel[1]  = fmaf(s, m0.y, rel[1]);
        rel[2]  = fmaf(s, m0.z, rel[2]);
        rel[3]  = fmaf(s, m0.w, rel[3]);
        rel[4]  = fmaf(s, m1.x, rel[4]);
        rel[5]  = fmaf(s, m1.y, rel[5]);
        rel[6]  = fmaf(s, m1.z, rel[6]);
        rel[7]  = fmaf(s, m1.w, rel[7]);
        rel[8]  = fmaf(s, m2.x, rel[8]);
        rel[9]  = fmaf(s, m2.y, rel[9]);
        rel[10] = fmaf(s, m2.z, rel[10]);
        rel[11] = fmaf(s, m2.w, rel[11]);
        rel[12] = fmaf(s, m3.x, rel[12]);
        rel[13] = fmaf(s, m3.y, rel[13]);
        rel[14] = fmaf(s, m3.z, rel[14]);
        rel[15] = fmaf(s, m3.w, rel[15]);
    }

    float dist = 0.0f;
    #pragma unroll
    for (int j = 0; j < 16; j++) {
        const float diff = fmaf(rel[j], inv_denom, ue[j] - ie[j]);
        dist = fmaf(diff, diff, dist);
    }
    dist += __shfl_xor_sync(0xFFFFFFFFu, dist, 1);

    if (p == 0 && valid) out[row] = -dist;
}

extern "C" void kernel_launch(void* const* d_in, const int* in_sizes, int n_in,
                              void* d_out, int out_size)
{
    const int*   user_ids = (const int*)  d_in[0];
    const int*   item_ids = (const int*)  d_in[1];
    const float* user_emb = (const float*)d_in[2];
    const float* item_emb = (const float*)d_in[3];
    const float* W_att    = (const float*)d_in[4];
    const float* memory   = (const float*)d_in[5];
    float*       out      = (float*)d_out;

    const int B = in_sizes[0];
    const int grid = (B + ROWS_PER_BLOCK - 1) / ROWS_PER_BLOCK;
    lrml_kernel<<<grid, THREADS>>>(user_ids, item_ids, user_emb, item_emb,
                                   W_att, memory, out, B);
}

// round 8
// speedup vs baseline: 1.3413x; 1.0337x over previous
#include <cuda_runtime.h>
#include <cuda_bf16.h>
#include <cstdint>

// LRML: out[b] = -|| ue + rel - ie ||^2
// Winning mapping from R7: 2 lanes/row, each lane owns 16 of D=32 dims,
// 16 rows per warp, single shfl_xor reductions.
// R8 change: 1 warp per block (32 threads), grid=1024 blocks -> all 148
// SMs active (~7 blocks/SM, co-resident, single wave), no cross-warp
// __syncthreads coupling; staging synchronized with __syncwarp only.

#define D 32
#define M 10
#define THREADS 32
#define ROWS_PER_WARP 16

__global__ __launch_bounds__(THREADS)
void lrml_kernel(const int* __restrict__ user_ids,
                 const int* __restrict__ item_ids,
                 const float* __restrict__ user_emb,
                 const float* __restrict__ item_emb,
                 const float* __restrict__ W_att,
                 const float* __restrict__ memory,
                 float* __restrict__ out,
                 int B)
{
    __shared__ float4 sW[M * 8];    // 10 rows x 32 floats as float4
    __shared__ float4 sMem[M * 8];

    const int lane = threadIdx.x & 31;
    const int p    = lane & 1;        // which 16-dim half
    const int r    = lane >> 1;       // row within warp (0..15)

    int row = blockIdx.x * ROWS_PER_WARP + r;
    const bool valid = (row < B);
    if (row >= B) row = B - 1;

    // ids first: their (L2/DRAM) latency overlaps the weight staging below
    const int uid = __ldg(&user_ids[row]);
    const int iid = __ldg(&item_ids[row]);

    // Stage weights (L2-hot, 2.5KB): 160 float4 by 32 threads = 5 each
    #pragma unroll
    for (int idx = lane; idx < M * 8; idx += THREADS) {
        sW[idx]   = __ldg(((const float4*)W_att) + idx);
        sMem[idx] = __ldg(((const float4*)memory) + idx);
    }

    // Gathers: each lane reads its 64B half-row from each table (4x LDG.128).
    // Both halves of a row share one 128B line -> minimal wavefronts.
    const float4* up = (const float4*)(user_emb + (size_t)uid * D + p * 16);
    const float4* ip = (const float4*)(item_emb + (size_t)iid * D + p * 16);
    const float4 u0 = __ldg(up);
    const float4 u1 = __ldg(up + 1);
    const float4 u2 = __ldg(up + 2);
    const float4 u3 = __ldg(up + 3);
    const float4 i0 = __ldg(ip);
    const float4 i1 = __ldg(ip + 1);
    const float4 i2 = __ldg(ip + 2);
    const float4 i3 = __ldg(ip + 3);

    __syncwarp();

    float ue[16] = {u0.x,u0.y,u0.z,u0.w, u1.x,u1.y,u1.z,u1.w,
                    u2.x,u2.y,u2.z,u2.w, u3.x,u3.y,u3.z,u3.w};
    float ie[16] = {i0.x,i0.y,i0.z,i0.w, i1.x,i1.y,i1.z,i1.w,
                    i2.x,i2.y,i2.z,i2.w, i3.x,i3.y,i3.z,i3.w};

    // max_norm=1 renorm (reduction = 1 shfl across the lane pair)
    float us = 0.f, is = 0.f;
    #pragma unroll
    for (int j = 0; j < 16; j++) { us = fmaf(ue[j], ue[j], us); is = fmaf(ie[j], ie[j], is); }
    us += __shfl_xor_sync(0xFFFFFFFFu, us, 1);
    is += __shfl_xor_sync(0xFFFFFFFFu, is, 1);
    const float un = sqrtf(us), in = sqrtf(is);
    const float uscale = (un > 1.0f) ? (1.0f / un) : 1.0f;
    const float iscale = (in > 1.0f) ? (1.0f / in) : 1.0f;
    #pragma unroll
    for (int j = 0; j < 16; j++) { ue[j] *= uscale; ie[j] *= iscale; }

    float joint[16];
    #pragma unroll
    for (int j = 0; j < 16; j++) joint[j] = ue[j] * ie[j];

    // scores[m] = joint . W_att[m] (16-dim partial + 1 shfl)
    float sc[M];
    #pragma unroll
    for (int m = 0; m < M; m++) {
        const float4* w = &sW[m * 8 + p * 4];
        const float4 w0 = w[0], w1 = w[1], w2 = w[2], w3 = w[3];
        float a = joint[0] * w0.x;
        float b = joint[1] * w0.y;
        a = fmaf(joint[2],  w0.z, a);
        b = fmaf(joint[3],  w0.w, b);
        a = fmaf(joint[4],  w1.x, a);
        b = fmaf(joint[5],  w1.y, b);
        a = fmaf(joint[6],  w1.z, a);
        b = fmaf(joint[7],  w1.w, b);
        a = fmaf(joint[8],  w2.x, a);
        b = fmaf(joint[9],  w2.y, b);
        a = fmaf(joint[10], w2.z, a);
        b = fmaf(joint[11], w2.w, b);
        a = fmaf(joint[12], w3.x, a);
        b = fmaf(joint[13], w3.y, b);
        a = fmaf(joint[14], w3.z, a);
        b = fmaf(joint[15], w3.w, b);
        float s = a + b;
        s += __shfl_xor_sync(0xFFFFFFFFu, s, 1);
        sc[m] = s;
    }

    // softmax over M=10, redundantly in both lanes of the pair
    float mx = sc[0];
    #pragma unroll
    for (int m = 1; m < M; m++) mx = fmaxf(mx, sc[m]);
    float denom = 0.0f;
    #pragma unroll
    for (int m = 0; m < M; m++) { sc[m] = __expf(sc[m] - mx); denom += sc[m]; }
    const float inv_denom = 1.0f / denom;

    // rel[j] = sum_m sc[m] * memory[m][p*16+j]; normalization folded into dist
    float rel[16];
    #pragma unroll
    for (int j = 0; j < 16; j++) rel[j] = 0.0f;
    #pragma unroll
    for (int m = 0; m < M; m++) {
        const float4* mmp = &sMem[m * 8 + p * 4];
        const float4 m0 = mmp[0], m1 = mmp[1], m2 = mmp[2], m3 = mmp[3];
        const float s = sc[m];
        rel[0]  = fmaf(s, m0.x, rel[0]);
        rel[1]  = fmaf(s, m0.y, rel[1]);
        rel[2]  = fmaf(s, m0.z, rel[2]);
        rel[3]  = fmaf(s, m0.w, rel[3]);
        rel[4]  = fmaf(s, m1.x, rel[4]);
        rel[5]  = fmaf(s, m1.y, rel[5]);
        rel[6]  = fmaf(s, m1.z, rel[6]);
        rel[7]  = fmaf(s, m1.w, rel[7]);
        rel[8]  = fmaf(s, m2.x, rel[8]);
        rel[9]  = fmaf(s, m2.y, rel[9]);
        rel[10] = fmaf(s, m2.z, rel[10]);
        rel[11] = fmaf(s, m2.w, rel[11]);
        rel[12] = fmaf(s, m3.x, rel[12]);
        rel[13] = fmaf(s, m3.y, rel[13]);
        rel[14] = fmaf(s, m3.z, rel[14]);
        rel[15] = fmaf(s, m3.w, rel[15]);
    }

    float dist = 0.0f;
    #pragma unroll
    for (int j = 0; j < 16; j++) {
        const float diff = fmaf(rel[j], inv_denom, ue[j] - ie[j]);
        dist = fmaf(diff, diff, dist);
    }
    dist += __shfl_xor_sync(0xFFFFFFFFu, dist, 1);

    if (p == 0 && valid) out[row] = -dist;
}

extern "C" void kernel_launch(void* const* d_in, const int* in_sizes, int n_in,
                              void* d_out, int out_size)
{
    const int*   user_ids = (const int*)  d_in[0];
    const int*   item_ids = (const int*)  d_in[1];
    const float* user_emb = (const float*)d_in[2];
    const float* item_emb = (const float*)d_in[3];
    const float* W_att    = (const float*)d_in[4];
    const float* memory   = (const float*)d_in[5];
    float*       out      = (float*)d_out;

    const int B = in_sizes[0];
    const int grid = (B + ROWS_PER_WARP - 1) / ROWS_PER_WARP;  // 1024
    lrml_kernel<<<grid, THREADS>>>(user_ids, item_ids, user_emb, item_emb,
                                   W_att, memory, out, B);
}